// round 2
// baseline (speedup 1.0000x reference)
#include <cuda_runtime.h>

// HyperConv2dDepthWise: per-batch-weight 5x5 depthwise conv + bias + SiLU
// input:  (16, 128, 128, 128) f32   -> 2048 planes of 128x128
// weights:(16, 3328) f32            -> per (b,c): 25 taps at b*3328+c*25, bias at b*3328+3200+c
// output: (16, 128, 128, 128) f32
//
// Strategy: CTA = one 32-row band of one plane. Stage band+halo in smem
// (zero-padded, no boundary branches). Warp = full row width (32 lanes x 4 cols,
// contiguous LDS.128). Each warp produces 8 rows as 4 vertical row-pairs using
// packed fp32x2 FMAs (fma.rn.f32x2) with a 6-row sliding register window.

#define HW      128
#define BAND    32
#define SROWS   (BAND + 4)     // 36
#define SPITCH  136            // floats; interior at col 4, halo cols 2,3 / 132,133 zeroed
#define NQ      (SPITCH / 4)   // 34 float4 per smem row
#define WSTRIDE 3328           // 25*128 + 128
#define BOFF    3200           // 25*128

typedef unsigned long long ull;

__device__ __forceinline__ ull pk2(float lo, float hi) {
    ull r;
    asm("mov.b64 %0, {%1, %2};" : "=l"(r) : "f"(lo), "f"(hi));
    return r;
}
__device__ __forceinline__ void fma2(ull& d, ull a, ull b) {
    asm("fma.rn.f32x2 %0, %1, %2, %0;" : "+l"(d) : "l"(a), "l"(b));
}
__device__ __forceinline__ float2 unpk(ull v) {
    float2 f;
    asm("mov.b64 {%0, %1}, %2;" : "=f"(f.x), "=f"(f.y) : "l"(v));
    return f;
}
__device__ __forceinline__ float silu_f(float x) {
    return x / (1.0f + __expf(-x));
}

__global__ __launch_bounds__(128, 3)
void hconv_dw_kernel(const float* __restrict__ input,
                     const float* __restrict__ wts,
                     float* __restrict__ out)
{
    __shared__ float smem[SROWS * SPITCH];

    const int bid   = blockIdx.x;
    const int band  = bid & 3;          // 4 bands per plane
    const int plane = bid >> 2;         // b*128 + c
    const int b     = plane >> 7;
    const int c     = plane & 127;
    const int r0    = band * BAND;

    const float* __restrict__ ip = input + (size_t)plane * (HW * HW);
    float* __restrict__ op       = out   + (size_t)plane * (HW * HW);

    const int tid = threadIdx.x;

    // ---- stage band (+2-row halo) into zero-padded smem ----
    // smem row y holds global row (r0 + y - 2); smem col (q*4..q*4+3);
    // interior quads q=1..32 map to logical cols (q-1)*4 .. +3; q=0 and q=33 are halo (zero).
    for (int i = tid; i < SROWS * NQ; i += 128) {
        const int y = i / NQ;
        const int q = i - y * NQ;
        const int g = r0 + y - 2;
        float4 v = make_float4(0.f, 0.f, 0.f, 0.f);
        if (q >= 1 && q <= 32 && g >= 0 && g < HW)
            v = *(const float4*)(ip + g * HW + (q - 1) * 4);
        *(float4*)(smem + y * SPITCH + q * 4) = v;
    }

    // ---- per-plane weights: 25 taps packed (w,w) + bias ----
    const float* wp = wts + b * WSTRIDE + c * 25;
    ull w2[25];
#pragma unroll
    for (int t = 0; t < 25; t++) {
        const float w = __ldg(wp + t);
        w2[t] = pk2(w, w);
    }
    const float bias = __ldg(wts + b * WSTRIDE + BOFF + c);
    const ull bias2 = pk2(bias, bias);

    __syncthreads();

    // ---- compute: warp = full row width, 32 lanes x 4 cols ----
    const int warp = tid >> 5;
    const int lane = tid & 31;
    const int x0   = lane * 4;          // logical output col base (also smem col of quad0)
    const int br0  = warp * 8;          // band-local first output row of this warp

    // 6-row sliding window; row holds logical cols x0-2 .. x0+5 (8 floats)
    float win[6][8];

#pragma unroll
    for (int i = 0; i < 6; i++) {
        const float* p = smem + (br0 + i) * SPITCH + x0;
        float4 a = *(const float4*)(p);
        float4 m = *(const float4*)(p + 4);
        float4 e = *(const float4*)(p + 8);
        win[i][0] = a.z; win[i][1] = a.w;
        win[i][2] = m.x; win[i][3] = m.y; win[i][4] = m.z; win[i][5] = m.w;
        win[i][6] = e.x; win[i][7] = e.y;
    }

#pragma unroll
    for (int p = 0; p < 4; p++) {
        ull acc[4] = { bias2, bias2, bias2, bias2 };

#pragma unroll
        for (int i = 0; i < 5; i++) {
            // vertical pair rows: window rows (2p+i, 2p+i+1) in the ring
            ull pv[8];
#pragma unroll
            for (int cc = 0; cc < 8; cc++)
                pv[cc] = pk2(win[(2 * p + i) % 6][cc], win[(2 * p + i + 1) % 6][cc]);
#pragma unroll
            for (int j = 0; j < 5; j++) {
#pragma unroll
                for (int cc = 0; cc < 4; cc++)
                    fma2(acc[cc], w2[i * 5 + j], pv[cc + j]);
            }
        }

        // epilogue: SiLU + store two rows (float4, coalesced)
        const int gy = r0 + br0 + 2 * p;
        const float2 t0 = unpk(acc[0]);
        const float2 t1 = unpk(acc[1]);
        const float2 t2 = unpk(acc[2]);
        const float2 t3 = unpk(acc[3]);
        float4 o0 = make_float4(silu_f(t0.x), silu_f(t1.x), silu_f(t2.x), silu_f(t3.x));
        float4 o1 = make_float4(silu_f(t0.y), silu_f(t1.y), silu_f(t2.y), silu_f(t3.y));
        *(float4*)(op + gy * HW + x0)       = o0;
        *(float4*)(op + (gy + 1) * HW + x0) = o1;

        // slide window by 2 rows (ring: overwrite the two oldest)
        if (p < 3) {
#pragma unroll
            for (int n = 0; n < 2; n++) {
                const int widx = (2 * p + n) % 6;           // == (2p+6+n) % 6
                const float* q = smem + (br0 + 2 * p + 6 + n) * SPITCH + x0;
                float4 a = *(const float4*)(q);
                float4 m = *(const float4*)(q + 4);
                float4 e = *(const float4*)(q + 8);
                win[widx][0] = a.z; win[widx][1] = a.w;
                win[widx][2] = m.x; win[widx][3] = m.y; win[widx][4] = m.z; win[widx][5] = m.w;
                win[widx][6] = e.x; win[widx][7] = e.y;
            }
        }
    }
}

extern "C" void kernel_launch(void* const* d_in, const int* in_sizes, int n_in,
                              void* d_out, int out_size)
{
    const float* input = (const float*)d_in[0];
    const float* wts   = (const float*)d_in[1];
    float* out         = (float*)d_out;

    // 2048 planes x 4 bands
    hconv_dw_kernel<<<8192, 128>>>(input, wts, out);
}

// round 3
// speedup vs baseline: 2.3063x; 2.3063x over previous
#include <cuda_runtime.h>

// HyperConv2dDepthWise: per-batch-weight 5x5 depthwise conv + bias + SiLU
// input:  (16, 128, 128, 128) f32   -> 2048 planes of 128x128
// weights:(16, 3328) f32            -> per (b,c): 25 taps at b*3328+c*25, bias at b*3328+3200+c
// output: (16, 128, 128, 128) f32
//
// Round-2 strategy: horizontal f32x2 packing. CTA = 32-row band of one plane,
// staged in zero-padded smem. Warp = full row width (32 lanes x 4 cols). Each
// lane's 4 outputs per row = 2 packed f32x2 accumulators. Even-aligned input
// pairs come directly from aligned halves of LDS.128 loads (no MOVs); only 3
// odd-aligned packs per input row, built once at row-load time. Inner loop is
// pure FFMA2 (10 per input-row contribution). 5-row packed sliding window.

#define HW      128
#define BAND    32
#define SROWS   (BAND + 4)     // 36
#define SPITCH  136            // floats; logical col L lives at smem col L+4
#define WSTRIDE 3328           // 25*128 + 128
#define BOFF    3200           // 25*128

typedef unsigned long long ull;

__device__ __forceinline__ ull pk2(float lo, float hi) {
    ull r;
    asm("mov.b64 %0, {%1, %2};" : "=l"(r) : "f"(lo), "f"(hi));
    return r;
}
__device__ __forceinline__ void fma2(ull& d, ull a, ull b) {
    asm("fma.rn.f32x2 %0, %1, %2, %0;" : "+l"(d) : "l"(a), "l"(b));
}
__device__ __forceinline__ float2 unpk(ull v) {
    float2 f;
    asm("mov.b64 {%0, %1}, %2;" : "=f"(f.x), "=f"(f.y) : "l"(v));
    return f;
}
__device__ __forceinline__ float silu_f(float x) {
    return __fdividef(x, 1.0f + __expf(-x));
}

// One packed window row: covers logical cols x0-2 .. x0+5.
// E0=(x-2,x-1) E1=(x,x+1) E2=(x+2,x+3) E3=(x+4,x+5)  <- aligned pairs, free
// O0=(x-1,x)   O1=(x+1,x+2) O2=(x+3,x+4)             <- 3 packs per row
struct WRow {
    ull E0, E1, E2, E3, O0, O1, O2;
};

__device__ __forceinline__ WRow load_row(const float* __restrict__ p) {
    // p = &smem[row][x0]  (smem col x0 == logical col x0-4), 16B aligned
    float4 A = *(const float4*)(p);      // logical x0-4 .. x0-1
    float4 B = *(const float4*)(p + 4);  // logical x0   .. x0+3
    float4 C = *(const float4*)(p + 8);  // logical x0+4 .. x0+7
    WRow r;
    r.E0 = pk2(A.z, A.w);   // aligned half of A -> MOVs elidable
    r.E1 = pk2(B.x, B.y);
    r.E2 = pk2(B.z, B.w);
    r.E3 = pk2(C.x, C.y);
    r.O0 = pk2(A.w, B.x);
    r.O1 = pk2(B.y, B.z);
    r.O2 = pk2(B.w, C.x);
    return r;
}

__global__ __launch_bounds__(128, 3)
void hconv_dw_kernel(const float* __restrict__ input,
                     const float* __restrict__ wts,
                     float* __restrict__ out)
{
    __shared__ float smem[SROWS * SPITCH];

    const int bid   = blockIdx.x;
    const int band  = bid & 3;          // 4 bands per plane
    const int plane = bid >> 2;         // b*128 + c
    const int b     = plane >> 7;
    const int c     = plane & 127;
    const int r0    = band * BAND;

    const float* __restrict__ ip = input + (size_t)plane * (HW * HW);
    float* __restrict__ op       = out   + (size_t)plane * (HW * HW);

    const int tid = threadIdx.x;

    // ---- stage band (+2-row halo) into zero-padded smem ----
    // smem row y holds global row (r0 + y - 2); interior cols 4..131.
    {
        const int lq = tid & 31;        // interior quad: logical col lq*4
        const int lr = tid >> 5;        // 0..3
        const float4 z4 = make_float4(0.f, 0.f, 0.f, 0.f);
#pragma unroll
        for (int k = 0; k < 9; k++) {
            const int y = lr + k * 4;   // 0..35
            const int g = r0 + y - 2;
            float4 v = z4;
            if (g >= 0 && g < HW)
                v = *(const float4*)(ip + g * HW + lq * 4);
            *(float4*)(smem + y * SPITCH + 4 + lq * 4) = v;
        }
        // zero halo columns: smem quads 0 and 33, all 36 rows (72 stores)
        if (tid < 72) {
            const int y = tid >> 1;
            const int q = (tid & 1) ? 33 : 0;
            *(float4*)(smem + y * SPITCH + q * 4) = z4;
        }
    }

    // ---- per-plane weights: 25 taps packed (w,w) + bias ----
    const float* wp = wts + b * WSTRIDE + c * 25;
    ull w2[25];
#pragma unroll
    for (int t = 0; t < 25; t++) {
        const float w = __ldg(wp + t);
        w2[t] = pk2(w, w);
    }
    const float bias = __ldg(wts + b * WSTRIDE + BOFF + c);
    const ull bias2 = pk2(bias, bias);

    __syncthreads();

    // ---- compute: warp = full row width, 32 lanes x 4 cols ----
    const int warp = tid >> 5;
    const int lane = tid & 31;
    const int x0   = lane * 4;          // logical output col base
    const int br0  = warp * 8;          // band-local first output row

    // warp needs smem rows br0 .. br0+11 (global rows r0+br0-2 .. r0+br0+9)
    WRow win[5];
#pragma unroll
    for (int y = 0; y < 4; y++)
        win[y] = load_row(smem + (br0 + y) * SPITCH + x0);

#pragma unroll
    for (int i = 0; i < 8; i++) {
        // load the new bottom row into ring slot (i+4)%5; it is consumed by
        // weight row d=4 (last), so 40 FFMA2 hide the LDS latency.
        win[(i + 4) % 5] = load_row(smem + (br0 + i + 4) * SPITCH + x0);

        ull acc0 = bias2, acc1 = bias2;
#pragma unroll
        for (int d = 0; d < 5; d++) {
            const WRow& r = win[(i + d) % 5];
            fma2(acc0, w2[d * 5 + 0], r.E0);  fma2(acc1, w2[d * 5 + 0], r.E1);
            fma2(acc0, w2[d * 5 + 1], r.O0);  fma2(acc1, w2[d * 5 + 1], r.O1);
            fma2(acc0, w2[d * 5 + 2], r.E1);  fma2(acc1, w2[d * 5 + 2], r.E2);
            fma2(acc0, w2[d * 5 + 3], r.O1);  fma2(acc1, w2[d * 5 + 3], r.O2);
            fma2(acc0, w2[d * 5 + 4], r.E2);  fma2(acc1, w2[d * 5 + 4], r.E3);
        }

        // epilogue: SiLU + coalesced float4 store
        const float2 a = unpk(acc0);
        const float2 bb = unpk(acc1);
        float4 o = make_float4(silu_f(a.x), silu_f(a.y), silu_f(bb.x), silu_f(bb.y));
        *(float4*)(op + (r0 + br0 + i) * HW + x0) = o;
    }
}

extern "C" void kernel_launch(void* const* d_in, const int* in_sizes, int n_in,
                              void* d_out, int out_size)
{
    const float* input = (const float*)d_in[0];
    const float* wts   = (const float*)d_in[1];
    float* out         = (float*)d_out;

    // 2048 planes x 4 bands
    hconv_dw_kernel<<<8192, 128>>>(input, wts, out);
}